// round 13
// baseline (speedup 1.0000x reference)
#include <cuda_runtime.h>
#include <math.h>
#include <stdint.h>

// ---------------- problem constants ----------------
#define Bq   2
#define Cq   768
#define Hq   256
#define Wq   256
#define NBq  8
#define BSq  96          // channels per block
#define KMq  103         // kept W modes  (int(129*0.8))
#define LOW  26          // band lo in H-frequency
#define BHq  206         // band height (hi-lo = 232-26)
#define NPTS (BHq*KMq)   // 21218 band points per (b,blk)
#define NTILE ((NPTS + 31) / 32)   // 664 point-tiles of 32

// ---------------- scratch (device globals; allocation-free rule) ----------------
// g_FA serves two roles (same element count 1536*103*256):
//   after K1: [(bc*103 + k)*256 + h]   (row-FFT bins, column-major-ish for col FFT)
//   after K4: [(bc*256 + h)*103 + k]   (inverse-col output, row-major for row iFFT)
__device__ float2 g_FA[(size_t)Bq * Cq * KMq * Hq];          // ~324 MB
// g_FB: band spectrum, [ (b*NB+blk) ][ i ][ pt = hp*103 + k ]  (MLP in-place)
__device__ float2 g_FB[(size_t)Bq * NBq * BSq * NPTS];       // ~260 MB
// output-paired weights: for output pair (2j, 2j+1) of input row i:
//   .x = pack(wr_{2j}, wr_{2j+1}),  .y = pack(wi_{2j}, wi_{2j+1})
// layout: [blk][i][j]  with j in 0..47
__device__ ulonglong2 g_W1p[NBq * BSq * (BSq / 2)];
__device__ ulonglong2 g_W2p[NBq * BSq * (BSq / 2)];

// ---------------- small helpers ----------------
__device__ __forceinline__ float2 cmulf(float2 a, float2 b) {
    return make_float2(a.x * b.x - a.y * b.y, a.x * b.y + a.y * b.x);
}

__device__ __forceinline__ unsigned long long pkf2(float lo, float hi) {
    unsigned long long r;
    asm("mov.b64 %0, {%1, %2};" : "=l"(r) : "f"(lo), "f"(hi));
    return r;
}
__device__ __forceinline__ void upkf2(unsigned long long v, float& lo, float& hi) {
    asm("mov.b64 {%0, %1}, %2;" : "=f"(lo), "=f"(hi) : "l"(v));
}
// packed dual FMA: acc(lo,hi) += a(lo,hi) * w(lo,hi)  elementwise
__device__ __forceinline__ void cfma2(unsigned long long& acc,
                                      unsigned long long a,
                                      unsigned long long w) {
    asm("fma.rn.f32x2 %0, %1, %2, %0;" : "+l"(acc) : "l"(a), "l"(w));
}

__device__ __forceinline__ float sshrink(float v) {
    float t = fabsf(v) - 0.01f;
    return (t > 0.f) ? copysignf(t, v) : 0.f;
}

// ---------------- warp-cooperative 256-pt Stockham radix-4 FFT ----------------
// buf0/buf1: this warp's two 256-complex smem buffers. Result lands in buf0,
// natural order. SIGN=-1 forward (e^{-i}), SIGN=+1 inverse (e^{+i}, unnormalized).
template <int SIGN>
__device__ __forceinline__ void fft256_warp(float2* buf0, float2* buf1, int lane) {
    __syncwarp();
    float2* src = buf0;
    float2* dst = buf1;
#pragma unroll
    for (int t = 0; t < 4; ++t) {
        const int s = 1 << (2 * t);
#pragma unroll
        for (int r = 0; r < 2; ++r) {
            const int u = lane + 32 * r;            // butterfly index 0..63
            const int p = u >> (2 * t);
            const int unit = u & ~(s - 1);          // = p * s
            float ang = (float)SIGN * 6.28318530717958647692f * (float)unit * (1.0f / 256.0f);
            float sn, cs;
            __sincosf(ang, &sn, &cs);
            float2 w1 = make_float2(cs, sn);
            float2 w2 = cmulf(w1, w1);
            float2 w3 = cmulf(w2, w1);
            float2 a = src[u];
            float2 b = src[u + 64];
            float2 c = src[u + 128];
            float2 d = src[u + 192];
            float2 apc = make_float2(a.x + c.x, a.y + c.y);
            float2 amc = make_float2(a.x - c.x, a.y - c.y);
            float2 bpd = make_float2(b.x + d.x, b.y + d.y);
            float2 bmd = make_float2(b.x - d.x, b.y - d.y);
            // forward: j*(b-d) with j=+i ; inverse: -i*(b-d)
            float2 jb = (SIGN < 0) ? make_float2(-bmd.y, bmd.x)
                                   : make_float2(bmd.y, -bmd.x);
            const int base = u + 3 * s * p;
            dst[base]         = make_float2(apc.x + bpd.x, apc.y + bpd.y);
            dst[base + s]     = cmulf(w1, make_float2(amc.x - jb.x, amc.y - jb.y));
            dst[base + 2 * s] = cmulf(w2, make_float2(apc.x - bpd.x, apc.y - bpd.y));
            dst[base + 3 * s] = cmulf(w3, make_float2(amc.x + jb.x, amc.y + jb.y));
        }
        __syncwarp();
        float2* tmp = src; src = dst; dst = tmp;
    }
}

// ---------------- K0: pre-swizzle MLP weights into output-paired form ----------
__global__ __launch_bounds__(256) void k_prep(const float* __restrict__ w1,
                                              const float* __restrict__ w2) {
    int idx = blockIdx.x * 256 + threadIdx.x;    // pair index
    if (idx < NBq * BSq * (BSq / 2)) {
        // idx -> (row = blk*96+i, pair j): row*48 + j
        int row = idx / (BSq / 2);
        int j = idx % (BSq / 2);
        const float2* src1 = (const float2*)w1 + row * BSq + 2 * j;
        float2 wa = src1[0], wb = src1[1];
        g_W1p[idx] = make_ulonglong2(pkf2(wa.x, wb.x), pkf2(wa.y, wb.y));
        const float2* src2 = (const float2*)w2 + row * BSq + 2 * j;
        wa = src2[0]; wb = src2[1];
        g_W2p[idx] = make_ulonglong2(pkf2(wa.x, wb.x), pkf2(wa.y, wb.y));
    }
}

// ---------------- K1: forward row rFFT (along W), keep bins 0..102 ----------------
// CTA = 8 consecutive h-rows of one (b,c). Warp w -> row h0+w.
__global__ __launch_bounds__(256) void k_row_fwd(const float* __restrict__ x) {
    __shared__ float2 sbuf[8][2][256];   // 32 KB
    const int warp = threadIdx.x >> 5, lane = threadIdx.x & 31;
    const int bc = blockIdx.x >> 5;            // 0..1535
    const int h0 = (blockIdx.x & 31) << 3;
    const int h = h0 + warp;
    const float* row = x + ((size_t)bc * Hq + h) * Wq;
    float2* b0 = sbuf[warp][0];
#pragma unroll
    for (int j = 0; j < 8; ++j) {
        int n = lane + 32 * j;
        b0[n] = make_float2(row[n], 0.f);
    }
    fft256_warp<-1>(b0, sbuf[warp][1], lane);
    __syncthreads();
    // transpose-write: consecutive threads -> consecutive h (64B chunks)
    for (int l = threadIdx.x; l < KMq * 8; l += 256) {
        int w = l & 7, k = l >> 3;
        float2 v = sbuf[w][0][k];
        g_FA[((size_t)bc * KMq + k) * Hq + h0 + w] = make_float2(v.x * 0.0625f, v.y * 0.0625f);
    }
}

// ---------------- K2: forward column FFT (along H), keep band -> g_FB ----------------
// CTA = one (b,c), 8 consecutive k modes. Warp w -> mode k0+w.
__global__ __launch_bounds__(256) void k_col_fwd() {
    __shared__ float2 sbuf[8][2][256];
    const int warp = threadIdx.x >> 5, lane = threadIdx.x & 31;
    const int bc = blockIdx.x / 13;
    const int k0 = (blockIdx.x % 13) * 8;
    const int k = k0 + warp;
    if (k < KMq) {
        const float2* col = g_FA + ((size_t)bc * KMq + k) * Hq;
        float2* b0 = sbuf[warp][0];
#pragma unroll
        for (int j = 0; j < 8; ++j) {
            int n = lane + 32 * j;
            b0[n] = col[n];
        }
        fft256_warp<-1>(b0, sbuf[warp][1], lane);
    }
    __syncthreads();
    const int b = bc / Cq, c = bc % Cq;
    const size_t base_i = ((size_t)((b * NBq + c / BSq) * BSq + (c % BSq))) * (size_t)NPTS;
    for (int l = threadIdx.x; l < BHq * 8; l += 256) {
        int hp = l >> 3, kr = l & 7;
        if (k0 + kr < KMq) {
            float2 v = sbuf[kr][0][LOW + hp];
            g_FB[base_i + hp * KMq + (k0 + kr)] = make_float2(v.x * 0.0625f, v.y * 0.0625f);
        }
    }
}

// ---------------- K3: per-point complex MLP (in-place on g_FB) ----------------
// CTA = one (b,blk) x 32 band points. thread = (o-chunk of 12, point).
// Output-paired weights (one LDG.128 per two outputs). This round: force
// 4 CTAs/SM via launch_bounds minBlocksPerMultiprocessor -> <=64 regs ->
// occupancy ~50% (was 37% at 72 regs / 3 CTAs). Accumulators need only
// 24 regs; the shave comes out of ptxas prefetch depth, not spills (verify).
__global__ __launch_bounds__(256, 4) void k_mlp(const float2* __restrict__ b1v,
                                                const float2* __restrict__ b2v) {
    __shared__ float2 sA[BSq][32];   // 24 KB, reused for o1 after layer 1
    const int bk = blockIdx.x / NTILE;            // 0..15 = b*8+blk
    const int pt0 = (blockIdx.x % NTILE) * 32;
    const int blk = bk & 7;
    const size_t gbase = (size_t)bk * BSq * NPTS;

    for (int l = threadIdx.x; l < BSq * 32; l += 256) {
        int i = l >> 5, p = l & 31;
        int pt = pt0 + p;
        sA[i][p] = (pt < NPTS) ? g_FB[gbase + (size_t)i * NPTS + pt]
                               : make_float2(0.f, 0.f);
    }
    __syncthreads();

    const int p = threadIdx.x & 31;
    const int o0 = (threadIdx.x >> 5) * 12;      // 12 outputs = 6 pairs
    const int j0 = o0 >> 1;                      // first pair index

    unsigned long long accR[6], accI[6];

    // ---- layer 1 ----
    const ulonglong2* W1 = g_W1p + blk * BSq * (BSq / 2);
#pragma unroll
    for (int j = 0; j < 6; ++j) { accR[j] = 0ULL; accI[j] = 0ULL; }
    for (int i = 0; i < BSq; ++i) {
        float2 a = sA[i][p];
        float nay = -a.y;
        unsigned long long axx  = pkf2(a.x, a.x);
        unsigned long long ayy  = pkf2(a.y, a.y);
        unsigned long long anyy = pkf2(nay, nay);
        const ulonglong2* wrow = W1 + i * (BSq / 2) + j0;
#pragma unroll
        for (int j = 0; j < 6; ++j) {
            ulonglong2 wq = wrow[j];               // .x = (wr,wr'), .y = (wi,wi')
            cfma2(accR[j], axx,  wq.x);
            cfma2(accR[j], anyy, wq.y);
            cfma2(accI[j], axx,  wq.y);
            cfma2(accI[j], ayy,  wq.x);
        }
    }
    __syncthreads();   // all done reading sA
#pragma unroll
    for (int j = 0; j < 6; ++j) {
        float r0, r1, i0, i1;
        upkf2(accR[j], r0, r1);
        upkf2(accI[j], i0, i1);
        float2 ba = b1v[blk * BSq + o0 + 2 * j];
        float2 bb = b1v[blk * BSq + o0 + 2 * j + 1];
        sA[o0 + 2 * j][p]     = make_float2(fmaxf(r0 + ba.x, 0.f), fmaxf(i0 + ba.y, 0.f));
        sA[o0 + 2 * j + 1][p] = make_float2(fmaxf(r1 + bb.x, 0.f), fmaxf(i1 + bb.y, 0.f));
    }
    __syncthreads();

    // ---- layer 2 ----
    const ulonglong2* W2 = g_W2p + blk * BSq * (BSq / 2);
#pragma unroll
    for (int j = 0; j < 6; ++j) { accR[j] = 0ULL; accI[j] = 0ULL; }
    for (int i = 0; i < BSq; ++i) {
        float2 a = sA[i][p];
        float nay = -a.y;
        unsigned long long axx  = pkf2(a.x, a.x);
        unsigned long long ayy  = pkf2(a.y, a.y);
        unsigned long long anyy = pkf2(nay, nay);
        const ulonglong2* wrow = W2 + i * (BSq / 2) + j0;
#pragma unroll
        for (int j = 0; j < 6; ++j) {
            ulonglong2 wq = wrow[j];
            cfma2(accR[j], axx,  wq.x);
            cfma2(accR[j], anyy, wq.y);
            cfma2(accI[j], axx,  wq.y);
            cfma2(accI[j], ayy,  wq.x);
        }
    }
    const int pt = pt0 + p;
    if (pt < NPTS) {
#pragma unroll
        for (int j = 0; j < 6; ++j) {
            float r0, r1, i0, i1;
            upkf2(accR[j], r0, r1);
            upkf2(accI[j], i0, i1);
            float2 ba = b2v[blk * BSq + o0 + 2 * j];
            float2 bb = b2v[blk * BSq + o0 + 2 * j + 1];
            g_FB[gbase + (size_t)(o0 + 2 * j) * NPTS + pt] =
                make_float2(sshrink(r0 + ba.x), sshrink(i0 + ba.y));
            g_FB[gbase + (size_t)(o0 + 2 * j + 1) * NPTS + pt] =
                make_float2(sshrink(r1 + bb.x), sshrink(i1 + bb.y));
        }
    }
}

// ---------------- K4: inverse column FFT (along H), band -> full columns ----------------
__global__ __launch_bounds__(256) void k_col_inv() {
    __shared__ float2 sbuf[8][2][256];
    const int bc = blockIdx.x / 13;
    const int k0 = (blockIdx.x % 13) * 8;
    const int b = bc / Cq, c = bc % Cq;
    const size_t base_i = ((size_t)((b * NBq + c / BSq) * BSq + (c % BSq))) * (size_t)NPTS;

    // zero all 8 input buffers
    for (int l = threadIdx.x; l < 8 * 256; l += 256)
        sbuf[l >> 8][0][l & 255] = make_float2(0.f, 0.f);
    __syncthreads();
    // cooperative band load: consecutive threads -> consecutive k (64B chunks)
    for (int l = threadIdx.x; l < BHq * 8; l += 256) {
        int hp = l >> 3, kr = l & 7;
        if (k0 + kr < KMq)
            sbuf[kr][0][LOW + hp] = g_FB[base_i + hp * KMq + (k0 + kr)];
    }
    __syncthreads();
    const int warp = threadIdx.x >> 5, lane = threadIdx.x & 31;
    if (k0 + warp < KMq)
        fft256_warp<1>(sbuf[warp][0], sbuf[warp][1], lane);
    __syncthreads();
    // transpose-write to row-major [(bc*256+h)*103 + k]
    for (int l = threadIdx.x; l < 8 * 256; l += 256) {
        int kr = l & 7, h = l >> 3;
        int k = k0 + kr;
        if (k < KMq) {
            float2 v = sbuf[kr][0][h];
            g_FA[((size_t)bc * Hq + h) * KMq + k] = make_float2(v.x * 0.0625f, v.y * 0.0625f);
        }
    }
}

// ---------------- K5: inverse row rFFT (c2r along W) + residual add ----------------
__global__ __launch_bounds__(256) void k_row_inv(const float* __restrict__ x,
                                                 float* __restrict__ out) {
    __shared__ float2 sbuf[8][2][256];
    const int warp = threadIdx.x >> 5, lane = threadIdx.x & 31;
    const int bc = blockIdx.x >> 5;
    const int h = ((blockIdx.x & 31) << 3) + warp;
    const float2* src = g_FA + ((size_t)bc * Hq + h) * KMq;
    float2* b0 = sbuf[warp][0];
#pragma unroll
    for (int j = 0; j < 8; ++j) {
        int n = lane + 32 * j;
        float2 v;
        if (n == 0) {
            v = make_float2(src[0].x, 0.f);           // c2r ignores imag of bin 0
        } else if (n <= 102) {
            v = src[n];
        } else if (n >= 154) {
            float2 t = src[256 - n];                   // Hermitian extension
            v = make_float2(t.x, -t.y);
        } else {
            v = make_float2(0.f, 0.f);                 // bins 103..153 are zero
        }
        b0[n] = v;
    }
    fft256_warp<1>(b0, sbuf[warp][1], lane);
    const size_t ro = ((size_t)bc * Hq + h) * Wq;
#pragma unroll
    for (int j = 0; j < 8; ++j) {
        int n = lane + 32 * j;
        out[ro + n] = b0[n].x * 0.0625f + x[ro + n];
    }
}

// ---------------- launch ----------------
extern "C" void kernel_launch(void* const* d_in, const int* in_sizes, int n_in,
                              void* d_out, int out_size) {
    const float* x  = (const float*)d_in[0];
    const float* w1 = (const float*)d_in[1];
    const float* b1 = (const float*)d_in[2];
    const float* w2 = (const float*)d_in[3];
    const float* b2 = (const float*)d_in[4];
    float* out = (float*)d_out;
    (void)in_sizes; (void)n_in; (void)out_size;

    k_prep<<<(NBq * BSq * (BSq / 2) + 255) / 256, 256>>>(w1, w2);
    k_row_fwd<<<Bq * Cq * 32, 256>>>(x);
    k_col_fwd<<<Bq * Cq * 13, 256>>>();
    k_mlp<<<Bq * NBq * NTILE, 256>>>((const float2*)b1, (const float2*)b2);
    k_col_inv<<<Bq * Cq * 13, 256>>>();
    k_row_inv<<<Bq * Cq * 32, 256>>>(x, out);
}

// round 14
// speedup vs baseline: 1.3321x; 1.3321x over previous
#include <cuda_runtime.h>
#include <math.h>
#include <stdint.h>

// ---------------- problem constants ----------------
#define Bq   2
#define Cq   768
#define Hq   256
#define Wq   256
#define NBq  8
#define BSq  96          // channels per block
#define KMq  103         // kept W modes  (int(129*0.8))
#define LOW  26          // band lo in H-frequency
#define BHq  206         // band height (hi-lo = 232-26)
#define NPTS (BHq*KMq)   // 21218 band points per (b,blk)
#define TPTS 64          // points per CTA in k_mlp
#define NTILE ((NPTS + TPTS - 1) / TPTS)   // 332 point-tiles of 64

// ---------------- scratch (device globals; allocation-free rule) ----------------
// g_FA serves two roles (same element count 1536*103*256):
//   after K1: [(bc*103 + k)*256 + h]   (row-FFT bins, column-major-ish for col FFT)
//   after K4: [(bc*256 + h)*103 + k]   (inverse-col output, row-major for row iFFT)
__device__ float2 g_FA[(size_t)Bq * Cq * KMq * Hq];          // ~324 MB
// g_FB: band spectrum, [ (b*NB+blk) ][ i ][ pt = hp*103 + k ]  (MLP in-place)
__device__ float2 g_FB[(size_t)Bq * NBq * BSq * NPTS];       // ~260 MB
// output-paired weights: for output pair (2j, 2j+1) of input row i:
//   .x = pack(wr_{2j}, wr_{2j+1}),  .y = pack(wi_{2j}, wi_{2j+1})
// layout: [blk][i][j]  with j in 0..47
__device__ ulonglong2 g_W1p[NBq * BSq * (BSq / 2)];
__device__ ulonglong2 g_W2p[NBq * BSq * (BSq / 2)];

// ---------------- small helpers ----------------
__device__ __forceinline__ float2 cmulf(float2 a, float2 b) {
    return make_float2(a.x * b.x - a.y * b.y, a.x * b.y + a.y * b.x);
}

__device__ __forceinline__ unsigned long long pkf2(float lo, float hi) {
    unsigned long long r;
    asm("mov.b64 %0, {%1, %2};" : "=l"(r) : "f"(lo), "f"(hi));
    return r;
}
__device__ __forceinline__ void upkf2(unsigned long long v, float& lo, float& hi) {
    asm("mov.b64 {%0, %1}, %2;" : "=f"(lo), "=f"(hi) : "l"(v));
}
// packed dual FMA: acc(lo,hi) += a(lo,hi) * w(lo,hi)  elementwise
__device__ __forceinline__ void cfma2(unsigned long long& acc,
                                      unsigned long long a,
                                      unsigned long long w) {
    asm("fma.rn.f32x2 %0, %1, %2, %0;" : "+l"(acc) : "l"(a), "l"(w));
}

__device__ __forceinline__ float sshrink(float v) {
    float t = fabsf(v) - 0.01f;
    return (t > 0.f) ? copysignf(t, v) : 0.f;
}

// ---------------- warp-cooperative 256-pt Stockham radix-4 FFT ----------------
// buf0/buf1: this warp's two 256-complex smem buffers. Result lands in buf0,
// natural order. SIGN=-1 forward (e^{-i}), SIGN=+1 inverse (e^{+i}, unnormalized).
template <int SIGN>
__device__ __forceinline__ void fft256_warp(float2* buf0, float2* buf1, int lane) {
    __syncwarp();
    float2* src = buf0;
    float2* dst = buf1;
#pragma unroll
    for (int t = 0; t < 4; ++t) {
        const int s = 1 << (2 * t);
#pragma unroll
        for (int r = 0; r < 2; ++r) {
            const int u = lane + 32 * r;            // butterfly index 0..63
            const int p = u >> (2 * t);
            const int unit = u & ~(s - 1);          // = p * s
            float ang = (float)SIGN * 6.28318530717958647692f * (float)unit * (1.0f / 256.0f);
            float sn, cs;
            __sincosf(ang, &sn, &cs);
            float2 w1 = make_float2(cs, sn);
            float2 w2 = cmulf(w1, w1);
            float2 w3 = cmulf(w2, w1);
            float2 a = src[u];
            float2 b = src[u + 64];
            float2 c = src[u + 128];
            float2 d = src[u + 192];
            float2 apc = make_float2(a.x + c.x, a.y + c.y);
            float2 amc = make_float2(a.x - c.x, a.y - c.y);
            float2 bpd = make_float2(b.x + d.x, b.y + d.y);
            float2 bmd = make_float2(b.x - d.x, b.y - d.y);
            // forward: j*(b-d) with j=+i ; inverse: -i*(b-d)
            float2 jb = (SIGN < 0) ? make_float2(-bmd.y, bmd.x)
                                   : make_float2(bmd.y, -bmd.x);
            const int base = u + 3 * s * p;
            dst[base]         = make_float2(apc.x + bpd.x, apc.y + bpd.y);
            dst[base + s]     = cmulf(w1, make_float2(amc.x - jb.x, amc.y - jb.y));
            dst[base + 2 * s] = cmulf(w2, make_float2(apc.x - bpd.x, apc.y - bpd.y));
            dst[base + 3 * s] = cmulf(w3, make_float2(amc.x + jb.x, amc.y + jb.y));
        }
        __syncwarp();
        float2* tmp = src; src = dst; dst = tmp;
    }
}

// ---------------- K0: pre-swizzle MLP weights into output-paired form ----------
__global__ __launch_bounds__(256) void k_prep(const float* __restrict__ w1,
                                              const float* __restrict__ w2) {
    int idx = blockIdx.x * 256 + threadIdx.x;    // pair index
    if (idx < NBq * BSq * (BSq / 2)) {
        // idx -> (row = blk*96+i, pair j): row*48 + j
        int row = idx / (BSq / 2);
        int j = idx % (BSq / 2);
        const float2* src1 = (const float2*)w1 + row * BSq + 2 * j;
        float2 wa = src1[0], wb = src1[1];
        g_W1p[idx] = make_ulonglong2(pkf2(wa.x, wb.x), pkf2(wa.y, wb.y));
        const float2* src2 = (const float2*)w2 + row * BSq + 2 * j;
        wa = src2[0]; wb = src2[1];
        g_W2p[idx] = make_ulonglong2(pkf2(wa.x, wb.x), pkf2(wa.y, wb.y));
    }
}

// ---------------- K1: forward row rFFT (along W), keep bins 0..102 ----------------
// CTA = 8 consecutive h-rows of one (b,c). Warp w -> row h0+w.
__global__ __launch_bounds__(256) void k_row_fwd(const float* __restrict__ x) {
    __shared__ float2 sbuf[8][2][256];   // 32 KB
    const int warp = threadIdx.x >> 5, lane = threadIdx.x & 31;
    const int bc = blockIdx.x >> 5;            // 0..1535
    const int h0 = (blockIdx.x & 31) << 3;
    const int h = h0 + warp;
    const float* row = x + ((size_t)bc * Hq + h) * Wq;
    float2* b0 = sbuf[warp][0];
#pragma unroll
    for (int j = 0; j < 8; ++j) {
        int n = lane + 32 * j;
        b0[n] = make_float2(row[n], 0.f);
    }
    fft256_warp<-1>(b0, sbuf[warp][1], lane);
    __syncthreads();
    // transpose-write: consecutive threads -> consecutive h (64B chunks)
    for (int l = threadIdx.x; l < KMq * 8; l += 256) {
        int w = l & 7, k = l >> 3;
        float2 v = sbuf[w][0][k];
        g_FA[((size_t)bc * KMq + k) * Hq + h0 + w] = make_float2(v.x * 0.0625f, v.y * 0.0625f);
    }
}

// ---------------- K2: forward column FFT (along H), keep band -> g_FB ----------------
// CTA = one (b,c), 8 consecutive k modes. Warp w -> mode k0+w.
__global__ __launch_bounds__(256) void k_col_fwd() {
    __shared__ float2 sbuf[8][2][256];
    const int warp = threadIdx.x >> 5, lane = threadIdx.x & 31;
    const int bc = blockIdx.x / 13;
    const int k0 = (blockIdx.x % 13) * 8;
    const int k = k0 + warp;
    if (k < KMq) {
        const float2* col = g_FA + ((size_t)bc * KMq + k) * Hq;
        float2* b0 = sbuf[warp][0];
#pragma unroll
        for (int j = 0; j < 8; ++j) {
            int n = lane + 32 * j;
            b0[n] = col[n];
        }
        fft256_warp<-1>(b0, sbuf[warp][1], lane);
    }
    __syncthreads();
    const int b = bc / Cq, c = bc % Cq;
    const size_t base_i = ((size_t)((b * NBq + c / BSq) * BSq + (c % BSq))) * (size_t)NPTS;
    for (int l = threadIdx.x; l < BHq * 8; l += 256) {
        int hp = l >> 3, kr = l & 7;
        if (k0 + kr < KMq) {
            float2 v = sbuf[kr][0][LOW + hp];
            g_FB[base_i + hp * KMq + (k0 + kr)] = make_float2(v.x * 0.0625f, v.y * 0.0625f);
        }
    }
}

// ---------------- K3: per-point complex MLP (in-place on g_FB) ----------------
// CTA = one (b,blk) x 64 band points; thread = (o-chunk of 12, point pair).
// Point layout in smem is interleaved (col 2p <-> point p, col 2p+1 <-> point
// p+32) so each i-step needs ONE LDS.128 per thread for both points. Combined
// with output-paired weights (6 uniform LDG.128 per warp per i feeding 48
// packed FMAs) this gives 0.21 L1 wavefronts per FMA vs 0.33 in the 1-point
// version, at ~80 regs (24 accumulator ull + 6 broadcast ull).
__global__ __launch_bounds__(256) void k_mlp(const float2* __restrict__ b1v,
                                             const float2* __restrict__ b2v) {
    __shared__ float2 sA[BSq][TPTS];   // 48 KB, reused for o1 after layer 1
    const int bk = blockIdx.x / NTILE;            // 0..15 = b*8+blk
    const int pt0 = (blockIdx.x % NTILE) * TPTS;
    const int blk = bk & 7;
    const size_t gbase = (size_t)bk * BSq * NPTS;

    // fill: col = 2*(pt&31) + (pt>>5)  <=>  pt = (col>>1) + (col&1)*32
    for (int l = threadIdx.x; l < BSq * TPTS; l += 256) {
        int i = l >> 6, col = l & 63;
        int pt = pt0 + (col >> 1) + ((col & 1) << 5);
        sA[i][col] = (pt < NPTS) ? g_FB[gbase + (size_t)i * NPTS + pt]
                                 : make_float2(0.f, 0.f);
    }
    __syncthreads();

    const int p = threadIdx.x & 31;        // lane -> points p (A) and p+32 (B)
    const int o0 = (threadIdx.x >> 5) * 12;      // 12 outputs = 6 pairs
    const int j0 = o0 >> 1;                      // first pair index

    unsigned long long accR0[6], accI0[6], accR1[6], accI1[6];

    // ---- layer 1 ----
    const ulonglong2* W1 = g_W1p + blk * BSq * (BSq / 2);
#pragma unroll
    for (int j = 0; j < 6; ++j) {
        accR0[j] = 0ULL; accI0[j] = 0ULL; accR1[j] = 0ULL; accI1[j] = 0ULL;
    }
    for (int i = 0; i < BSq; ++i) {
        float4 av = ((const float4*)sA[i])[p];   // (A.re, A.im, B.re, B.im)
        unsigned long long axx0  = pkf2(av.x, av.x);
        unsigned long long ayy0  = pkf2(av.y, av.y);
        unsigned long long anyy0 = pkf2(-av.y, -av.y);
        unsigned long long axx1  = pkf2(av.z, av.z);
        unsigned long long ayy1  = pkf2(av.w, av.w);
        unsigned long long anyy1 = pkf2(-av.w, -av.w);
        const ulonglong2* wrow = W1 + i * (BSq / 2) + j0;
#pragma unroll
        for (int j = 0; j < 6; ++j) {
            ulonglong2 wq = wrow[j];               // .x = (wr,wr'), .y = (wi,wi')
            cfma2(accR0[j], axx0,  wq.x);
            cfma2(accR0[j], anyy0, wq.y);
            cfma2(accI0[j], axx0,  wq.y);
            cfma2(accI0[j], ayy0,  wq.x);
            cfma2(accR1[j], axx1,  wq.x);
            cfma2(accR1[j], anyy1, wq.y);
            cfma2(accI1[j], axx1,  wq.y);
            cfma2(accI1[j], ayy1,  wq.x);
        }
    }
    __syncthreads();   // all done reading sA
#pragma unroll
    for (int j = 0; j < 6; ++j) {
        float2 ba = b1v[blk * BSq + o0 + 2 * j];
        float2 bb = b1v[blk * BSq + o0 + 2 * j + 1];
        float r0A, r1A, i0A, i1A, r0B, r1B, i0B, i1B;
        upkf2(accR0[j], r0A, r1A);
        upkf2(accI0[j], i0A, i1A);
        upkf2(accR1[j], r0B, r1B);
        upkf2(accI1[j], i0B, i1B);
        // row o0+2j: (A, B) ; row o0+2j+1: (A, B)
        ((float4*)sA[o0 + 2 * j])[p] =
            make_float4(fmaxf(r0A + ba.x, 0.f), fmaxf(i0A + ba.y, 0.f),
                        fmaxf(r0B + ba.x, 0.f), fmaxf(i0B + ba.y, 0.f));
        ((float4*)sA[o0 + 2 * j + 1])[p] =
            make_float4(fmaxf(r1A + bb.x, 0.f), fmaxf(i1A + bb.y, 0.f),
                        fmaxf(r1B + bb.x, 0.f), fmaxf(i1B + bb.y, 0.f));
    }
    __syncthreads();

    // ---- layer 2 ----
    const ulonglong2* W2 = g_W2p + blk * BSq * (BSq / 2);
#pragma unroll
    for (int j = 0; j < 6; ++j) {
        accR0[j] = 0ULL; accI0[j] = 0ULL; accR1[j] = 0ULL; accI1[j] = 0ULL;
    }
    for (int i = 0; i < BSq; ++i) {
        float4 av = ((const float4*)sA[i])[p];
        unsigned long long axx0  = pkf2(av.x, av.x);
        unsigned long long ayy0  = pkf2(av.y, av.y);
        unsigned long long anyy0 = pkf2(-av.y, -av.y);
        unsigned long long axx1  = pkf2(av.z, av.z);
        unsigned long long ayy1  = pkf2(av.w, av.w);
        unsigned long long anyy1 = pkf2(-av.w, -av.w);
        const ulonglong2* wrow = W2 + i * (BSq / 2) + j0;
#pragma unroll
        for (int j = 0; j < 6; ++j) {
            ulonglong2 wq = wrow[j];
            cfma2(accR0[j], axx0,  wq.x);
            cfma2(accR0[j], anyy0, wq.y);
            cfma2(accI0[j], axx0,  wq.y);
            cfma2(accI0[j], ayy0,  wq.x);
            cfma2(accR1[j], axx1,  wq.x);
            cfma2(accR1[j], anyy1, wq.y);
            cfma2(accI1[j], axx1,  wq.y);
            cfma2(accI1[j], ayy1,  wq.x);
        }
    }
    const int ptA = pt0 + p;
    const int ptB = pt0 + p + 32;
#pragma unroll
    for (int j = 0; j < 6; ++j) {
        float2 ba = b2v[blk * BSq + o0 + 2 * j];
        float2 bb = b2v[blk * BSq + o0 + 2 * j + 1];
        float r0A, r1A, i0A, i1A, r0B, r1B, i0B, i1B;
        upkf2(accR0[j], r0A, r1A);
        upkf2(accI0[j], i0A, i1A);
        upkf2(accR1[j], r0B, r1B);
        upkf2(accI1[j], i0B, i1B);
        if (ptA < NPTS) {
            g_FB[gbase + (size_t)(o0 + 2 * j) * NPTS + ptA] =
                make_float2(sshrink(r0A + ba.x), sshrink(i0A + ba.y));
            g_FB[gbase + (size_t)(o0 + 2 * j + 1) * NPTS + ptA] =
                make_float2(sshrink(r1A + bb.x), sshrink(i1A + bb.y));
        }
        if (ptB < NPTS) {
            g_FB[gbase + (size_t)(o0 + 2 * j) * NPTS + ptB] =
                make_float2(sshrink(r0B + ba.x), sshrink(i0B + ba.y));
            g_FB[gbase + (size_t)(o0 + 2 * j + 1) * NPTS + ptB] =
                make_float2(sshrink(r1B + bb.x), sshrink(i1B + bb.y));
        }
    }
}

// ---------------- K4: inverse column FFT (along H), band -> full columns ----------------
__global__ __launch_bounds__(256) void k_col_inv() {
    __shared__ float2 sbuf[8][2][256];
    const int bc = blockIdx.x / 13;
    const int k0 = (blockIdx.x % 13) * 8;
    const int b = bc / Cq, c = bc % Cq;
    const size_t base_i = ((size_t)((b * NBq + c / BSq) * BSq + (c % BSq))) * (size_t)NPTS;

    // zero all 8 input buffers
    for (int l = threadIdx.x; l < 8 * 256; l += 256)
        sbuf[l >> 8][0][l & 255] = make_float2(0.f, 0.f);
    __syncthreads();
    // cooperative band load: consecutive threads -> consecutive k (64B chunks)
    for (int l = threadIdx.x; l < BHq * 8; l += 256) {
        int hp = l >> 3, kr = l & 7;
        if (k0 + kr < KMq)
            sbuf[kr][0][LOW + hp] = g_FB[base_i + hp * KMq + (k0 + kr)];
    }
    __syncthreads();
    const int warp = threadIdx.x >> 5, lane = threadIdx.x & 31;
    if (k0 + warp < KMq)
        fft256_warp<1>(sbuf[warp][0], sbuf[warp][1], lane);
    __syncthreads();
    // transpose-write to row-major [(bc*256+h)*103 + k]
    for (int l = threadIdx.x; l < 8 * 256; l += 256) {
        int kr = l & 7, h = l >> 3;
        int k = k0 + kr;
        if (k < KMq) {
            float2 v = sbuf[kr][0][h];
            g_FA[((size_t)bc * Hq + h) * KMq + k] = make_float2(v.x * 0.0625f, v.y * 0.0625f);
        }
    }
}

// ---------------- K5: inverse row rFFT (c2r along W) + residual add ----------------
__global__ __launch_bounds__(256) void k_row_inv(const float* __restrict__ x,
                                                 float* __restrict__ out) {
    __shared__ float2 sbuf[8][2][256];
    const int warp = threadIdx.x >> 5, lane = threadIdx.x & 31;
    const int bc = blockIdx.x >> 5;
    const int h = ((blockIdx.x & 31) << 3) + warp;
    const float2* src = g_FA + ((size_t)bc * Hq + h) * KMq;
    float2* b0 = sbuf[warp][0];
#pragma unroll
    for (int j = 0; j < 8; ++j) {
        int n = lane + 32 * j;
        float2 v;
        if (n == 0) {
            v = make_float2(src[0].x, 0.f);           // c2r ignores imag of bin 0
        } else if (n <= 102) {
            v = src[n];
        } else if (n >= 154) {
            float2 t = src[256 - n];                   // Hermitian extension
            v = make_float2(t.x, -t.y);
        } else {
            v = make_float2(0.f, 0.f);                 // bins 103..153 are zero
        }
        b0[n] = v;
    }
    fft256_warp<1>(b0, sbuf[warp][1], lane);
    const size_t ro = ((size_t)bc * Hq + h) * Wq;
#pragma unroll
    for (int j = 0; j < 8; ++j) {
        int n = lane + 32 * j;
        out[ro + n] = b0[n].x * 0.0625f + x[ro + n];
    }
}

// ---------------- launch ----------------
extern "C" void kernel_launch(void* const* d_in, const int* in_sizes, int n_in,
                              void* d_out, int out_size) {
    const float* x  = (const float*)d_in[0];
    const float* w1 = (const float*)d_in[1];
    const float* b1 = (const float*)d_in[2];
    const float* w2 = (const float*)d_in[3];
    const float* b2 = (const float*)d_in[4];
    float* out = (float*)d_out;
    (void)in_sizes; (void)n_in; (void)out_size;

    k_prep<<<(NBq * BSq * (BSq / 2) + 255) / 256, 256>>>(w1, w2);
    k_row_fwd<<<Bq * Cq * 32, 256>>>(x);
    k_col_fwd<<<Bq * Cq * 13, 256>>>();
    k_mlp<<<Bq * NBq * NTILE, 256>>>((const float2*)b1, (const float2*)b2);
    k_col_inv<<<Bq * Cq * 13, 256>>>();
    k_row_inv<<<Bq * Cq * 32, 256>>>(x, out);
}

// round 15
// speedup vs baseline: 1.5320x; 1.1500x over previous
#include <cuda_runtime.h>
#include <math.h>
#include <stdint.h>

// ---------------- problem constants ----------------
#define Bq   2
#define Cq   768
#define Hq   256
#define Wq   256
#define NBq  8
#define BSq  96          // channels per block
#define KMq  103         // kept W modes  (int(129*0.8))
#define LOW  26          // band lo in H-frequency
#define BHq  206         // band height (hi-lo = 232-26)
#define NPTS (BHq*KMq)   // 21218 band points per (b,blk)
#define TPTS 64          // points per CTA in k_mlp
#define NTILE ((NPTS + TPTS - 1) / TPTS)   // 332 point-tiles of 64

// ---------------- scratch (device globals; allocation-free rule) ----------------
__device__ float2 g_FA[(size_t)Bq * Cq * KMq * Hq];          // ~324 MB
__device__ float2 g_FB[(size_t)Bq * NBq * BSq * NPTS];       // ~260 MB
// output-paired weights: .x = pack(wr_{2j}, wr_{2j+1}), .y = pack(wi_{2j}, wi_{2j+1})
__device__ ulonglong2 g_W1p[NBq * BSq * (BSq / 2)];
__device__ ulonglong2 g_W2p[NBq * BSq * (BSq / 2)];

// ---------------- small helpers ----------------
__device__ __forceinline__ float2 cmulf(float2 a, float2 b) {
    return make_float2(a.x * b.x - a.y * b.y, a.x * b.y + a.y * b.x);
}

__device__ __forceinline__ unsigned long long pkf2(float lo, float hi) {
    unsigned long long r;
    asm("mov.b64 %0, {%1, %2};" : "=l"(r) : "f"(lo), "f"(hi));
    return r;
}
__device__ __forceinline__ void upkf2(unsigned long long v, float& lo, float& hi) {
    asm("mov.b64 {%0, %1}, %2;" : "=f"(lo), "=f"(hi) : "l"(v));
}
__device__ __forceinline__ void cfma2(unsigned long long& acc,
                                      unsigned long long a,
                                      unsigned long long w) {
    asm("fma.rn.f32x2 %0, %1, %2, %0;" : "+l"(acc) : "l"(a), "l"(w));
}

__device__ __forceinline__ float sshrink(float v) {
    float t = fabsf(v) - 0.01f;
    return (t > 0.f) ? copysignf(t, v) : 0.f;
}

// ---------------- warp-cooperative 256-pt Stockham radix-4 FFT ----------------
template <int SIGN>
__device__ __forceinline__ void fft256_warp(float2* buf0, float2* buf1, int lane) {
    __syncwarp();
    float2* src = buf0;
    float2* dst = buf1;
#pragma unroll
    for (int t = 0; t < 4; ++t) {
        const int s = 1 << (2 * t);
#pragma unroll
        for (int r = 0; r < 2; ++r) {
            const int u = lane + 32 * r;            // butterfly index 0..63
            const int p = u >> (2 * t);
            const int unit = u & ~(s - 1);          // = p * s
            float ang = (float)SIGN * 6.28318530717958647692f * (float)unit * (1.0f / 256.0f);
            float sn, cs;
            __sincosf(ang, &sn, &cs);
            float2 w1 = make_float2(cs, sn);
            float2 w2 = cmulf(w1, w1);
            float2 w3 = cmulf(w2, w1);
            float2 a = src[u];
            float2 b = src[u + 64];
            float2 c = src[u + 128];
            float2 d = src[u + 192];
            float2 apc = make_float2(a.x + c.x, a.y + c.y);
            float2 amc = make_float2(a.x - c.x, a.y - c.y);
            float2 bpd = make_float2(b.x + d.x, b.y + d.y);
            float2 bmd = make_float2(b.x - d.x, b.y - d.y);
            float2 jb = (SIGN < 0) ? make_float2(-bmd.y, bmd.x)
                                   : make_float2(bmd.y, -bmd.x);
            const int base = u + 3 * s * p;
            dst[base]         = make_float2(apc.x + bpd.x, apc.y + bpd.y);
            dst[base + s]     = cmulf(w1, make_float2(amc.x - jb.x, amc.y - jb.y));
            dst[base + 2 * s] = cmulf(w2, make_float2(apc.x - bpd.x, apc.y - bpd.y));
            dst[base + 3 * s] = cmulf(w3, make_float2(amc.x + jb.x, amc.y + jb.y));
        }
        __syncwarp();
        float2* tmp = src; src = dst; dst = tmp;
    }
}

// ---------------- K0: pre-swizzle MLP weights into output-paired form ----------
__global__ __launch_bounds__(256) void k_prep(const float* __restrict__ w1,
                                              const float* __restrict__ w2) {
    int idx = blockIdx.x * 256 + threadIdx.x;    // pair index
    if (idx < NBq * BSq * (BSq / 2)) {
        int row = idx / (BSq / 2);
        int j = idx % (BSq / 2);
        const float2* src1 = (const float2*)w1 + row * BSq + 2 * j;
        float2 wa = src1[0], wb = src1[1];
        g_W1p[idx] = make_ulonglong2(pkf2(wa.x, wb.x), pkf2(wa.y, wb.y));
        const float2* src2 = (const float2*)w2 + row * BSq + 2 * j;
        wa = src2[0]; wb = src2[1];
        g_W2p[idx] = make_ulonglong2(pkf2(wa.x, wb.x), pkf2(wa.y, wb.y));
    }
}

// ---------------- K1: forward row rFFT, TWO real rows per complex FFT ----------
// Warp w -> rows hA = h0+2w, hB = hA+1 packed as z = xA + i*xB.
// Unpack: X_a[k] = (Z[k]+conj(Z[256-k]))/2 ; X_b[k] = (Z[k]-conj(Z[256-k]))/(2i).
// h-pairs are adjacent in g_FA -> float4 band writes.
__global__ __launch_bounds__(256) void k_row_fwd(const float* __restrict__ x) {
    __shared__ float2 sbuf[8][2][256];   // 32 KB
    const int warp = threadIdx.x >> 5, lane = threadIdx.x & 31;
    const int bc = blockIdx.x >> 4;            // 0..1535
    const int h0 = (blockIdx.x & 15) << 4;     // 16 rows per CTA
    const int hA = h0 + 2 * warp;
    const float* rowA = x + ((size_t)bc * Hq + hA) * Wq;
    const float* rowB = rowA + Wq;
    float2* b0 = sbuf[warp][0];
#pragma unroll
    for (int j = 0; j < 8; ++j) {
        int n = lane + 32 * j;
        b0[n] = make_float2(rowA[n], rowB[n]);
    }
    fft256_warp<-1>(b0, sbuf[warp][1], lane);
    __syncthreads();
    // unpack + transpose-write: 8 threads per k cover 16 h (float4 chunks)
    for (int l = threadIdx.x; l < KMq * 8; l += 256) {
        int w = l & 7, k = l >> 3;
        const float2* buf = sbuf[w][0];
        float2 Za = buf[k];
        float2 Zb = buf[(256 - k) & 255];
        const float s = 0.03125f;   // 0.5 (unpack) * 0.0625 (ortho 1/sqrt(256))
        float4 v = make_float4((Za.x + Zb.x) * s, (Za.y - Zb.y) * s,
                               (Za.y + Zb.y) * s, (Zb.x - Za.x) * s);
        *(float4*)&g_FA[((size_t)bc * KMq + k) * Hq + h0 + 2 * w] = v;
    }
}

// ---------------- K2: forward column FFT (along H), keep band -> g_FB ----------------
__global__ __launch_bounds__(256) void k_col_fwd() {
    __shared__ float2 sbuf[8][2][256];
    const int warp = threadIdx.x >> 5, lane = threadIdx.x & 31;
    const int bc = blockIdx.x / 13;
    const int k0 = (blockIdx.x % 13) * 8;
    const int k = k0 + warp;
    if (k < KMq) {
        const float2* col = g_FA + ((size_t)bc * KMq + k) * Hq;
        float2* b0 = sbuf[warp][0];
#pragma unroll
        for (int j = 0; j < 8; ++j) {
            int n = lane + 32 * j;
            b0[n] = col[n];
        }
        fft256_warp<-1>(b0, sbuf[warp][1], lane);
    }
    __syncthreads();
    const int b = bc / Cq, c = bc % Cq;
    const size_t base_i = ((size_t)((b * NBq + c / BSq) * BSq + (c % BSq))) * (size_t)NPTS;
    for (int l = threadIdx.x; l < BHq * 8; l += 256) {
        int hp = l >> 3, kr = l & 7;
        if (k0 + kr < KMq) {
            float2 v = sbuf[kr][0][LOW + hp];
            g_FB[base_i + hp * KMq + (k0 + kr)] = make_float2(v.x * 0.0625f, v.y * 0.0625f);
        }
    }
}

// ---------------- K3: per-point complex MLP (in-place on g_FB) ----------------
// CTA = one (b,blk) x 64 band points; thread = (o-chunk of 12, point pair).
// UNCHANGED from R14 winner (1.03 ms, FMA 61.7%).
__global__ __launch_bounds__(256) void k_mlp(const float2* __restrict__ b1v,
                                             const float2* __restrict__ b2v) {
    __shared__ float2 sA[BSq][TPTS];   // 48 KB, reused for o1 after layer 1
    const int bk = blockIdx.x / NTILE;            // 0..15 = b*8+blk
    const int pt0 = (blockIdx.x % NTILE) * TPTS;
    const int blk = bk & 7;
    const size_t gbase = (size_t)bk * BSq * NPTS;

    // fill: col = 2*(pt&31) + (pt>>5)  <=>  pt = (col>>1) + (col&1)*32
    for (int l = threadIdx.x; l < BSq * TPTS; l += 256) {
        int i = l >> 6, col = l & 63;
        int pt = pt0 + (col >> 1) + ((col & 1) << 5);
        sA[i][col] = (pt < NPTS) ? g_FB[gbase + (size_t)i * NPTS + pt]
                                 : make_float2(0.f, 0.f);
    }
    __syncthreads();

    const int p = threadIdx.x & 31;        // lane -> points p (A) and p+32 (B)
    const int o0 = (threadIdx.x >> 5) * 12;      // 12 outputs = 6 pairs
    const int j0 = o0 >> 1;                      // first pair index

    unsigned long long accR0[6], accI0[6], accR1[6], accI1[6];

    // ---- layer 1 ----
    const ulonglong2* W1 = g_W1p + blk * BSq * (BSq / 2);
#pragma unroll
    for (int j = 0; j < 6; ++j) {
        accR0[j] = 0ULL; accI0[j] = 0ULL; accR1[j] = 0ULL; accI1[j] = 0ULL;
    }
    for (int i = 0; i < BSq; ++i) {
        float4 av = ((const float4*)sA[i])[p];   // (A.re, A.im, B.re, B.im)
        unsigned long long axx0  = pkf2(av.x, av.x);
        unsigned long long ayy0  = pkf2(av.y, av.y);
        unsigned long long anyy0 = pkf2(-av.y, -av.y);
        unsigned long long axx1  = pkf2(av.z, av.z);
        unsigned long long ayy1  = pkf2(av.w, av.w);
        unsigned long long anyy1 = pkf2(-av.w, -av.w);
        const ulonglong2* wrow = W1 + i * (BSq / 2) + j0;
#pragma unroll
        for (int j = 0; j < 6; ++j) {
            ulonglong2 wq = wrow[j];               // .x = (wr,wr'), .y = (wi,wi')
            cfma2(accR0[j], axx0,  wq.x);
            cfma2(accR0[j], anyy0, wq.y);
            cfma2(accI0[j], axx0,  wq.y);
            cfma2(accI0[j], ayy0,  wq.x);
            cfma2(accR1[j], axx1,  wq.x);
            cfma2(accR1[j], anyy1, wq.y);
            cfma2(accI1[j], axx1,  wq.y);
            cfma2(accI1[j], ayy1,  wq.x);
        }
    }
    __syncthreads();   // all done reading sA
#pragma unroll
    for (int j = 0; j < 6; ++j) {
        float2 ba = b1v[blk * BSq + o0 + 2 * j];
        float2 bb = b1v[blk * BSq + o0 + 2 * j + 1];
        float r0A, r1A, i0A, i1A, r0B, r1B, i0B, i1B;
        upkf2(accR0[j], r0A, r1A);
        upkf2(accI0[j], i0A, i1A);
        upkf2(accR1[j], r0B, r1B);
        upkf2(accI1[j], i0B, i1B);
        ((float4*)sA[o0 + 2 * j])[p] =
            make_float4(fmaxf(r0A + ba.x, 0.f), fmaxf(i0A + ba.y, 0.f),
                        fmaxf(r0B + ba.x, 0.f), fmaxf(i0B + ba.y, 0.f));
        ((float4*)sA[o0 + 2 * j + 1])[p] =
            make_float4(fmaxf(r1A + bb.x, 0.f), fmaxf(i1A + bb.y, 0.f),
                        fmaxf(r1B + bb.x, 0.f), fmaxf(i1B + bb.y, 0.f));
    }
    __syncthreads();

    // ---- layer 2 ----
    const ulonglong2* W2 = g_W2p + blk * BSq * (BSq / 2);
#pragma unroll
    for (int j = 0; j < 6; ++j) {
        accR0[j] = 0ULL; accI0[j] = 0ULL; accR1[j] = 0ULL; accI1[j] = 0ULL;
    }
    for (int i = 0; i < BSq; ++i) {
        float4 av = ((const float4*)sA[i])[p];
        unsigned long long axx0  = pkf2(av.x, av.x);
        unsigned long long ayy0  = pkf2(av.y, av.y);
        unsigned long long anyy0 = pkf2(-av.y, -av.y);
        unsigned long long axx1  = pkf2(av.z, av.z);
        unsigned long long ayy1  = pkf2(av.w, av.w);
        unsigned long long anyy1 = pkf2(-av.w, -av.w);
        const ulonglong2* wrow = W2 + i * (BSq / 2) + j0;
#pragma unroll
        for (int j = 0; j < 6; ++j) {
            ulonglong2 wq = wrow[j];
            cfma2(accR0[j], axx0,  wq.x);
            cfma2(accR0[j], anyy0, wq.y);
            cfma2(accI0[j], axx0,  wq.y);
            cfma2(accI0[j], ayy0,  wq.x);
            cfma2(accR1[j], axx1,  wq.x);
            cfma2(accR1[j], anyy1, wq.y);
            cfma2(accI1[j], axx1,  wq.y);
            cfma2(accI1[j], ayy1,  wq.x);
        }
    }
    const int ptA = pt0 + p;
    const int ptB = pt0 + p + 32;
#pragma unroll
    for (int j = 0; j < 6; ++j) {
        float2 ba = b2v[blk * BSq + o0 + 2 * j];
        float2 bb = b2v[blk * BSq + o0 + 2 * j + 1];
        float r0A, r1A, i0A, i1A, r0B, r1B, i0B, i1B;
        upkf2(accR0[j], r0A, r1A);
        upkf2(accI0[j], i0A, i1A);
        upkf2(accR1[j], r0B, r1B);
        upkf2(accI1[j], i0B, i1B);
        if (ptA < NPTS) {
            g_FB[gbase + (size_t)(o0 + 2 * j) * NPTS + ptA] =
                make_float2(sshrink(r0A + ba.x), sshrink(i0A + ba.y));
            g_FB[gbase + (size_t)(o0 + 2 * j + 1) * NPTS + ptA] =
                make_float2(sshrink(r1A + bb.x), sshrink(i1A + bb.y));
        }
        if (ptB < NPTS) {
            g_FB[gbase + (size_t)(o0 + 2 * j) * NPTS + ptB] =
                make_float2(sshrink(r0B + ba.x), sshrink(i0B + ba.y));
            g_FB[gbase + (size_t)(o0 + 2 * j + 1) * NPTS + ptB] =
                make_float2(sshrink(r1B + bb.x), sshrink(i1B + bb.y));
        }
    }
}

// ---------------- K4: inverse column FFT (along H), band -> full columns ----------------
__global__ __launch_bounds__(256) void k_col_inv() {
    __shared__ float2 sbuf[8][2][256];
    const int bc = blockIdx.x / 13;
    const int k0 = (blockIdx.x % 13) * 8;
    const int b = bc / Cq, c = bc % Cq;
    const size_t base_i = ((size_t)((b * NBq + c / BSq) * BSq + (c % BSq))) * (size_t)NPTS;

    // zero all 8 input buffers
    for (int l = threadIdx.x; l < 8 * 256; l += 256)
        sbuf[l >> 8][0][l & 255] = make_float2(0.f, 0.f);
    __syncthreads();
    // cooperative band load: consecutive threads -> consecutive k (64B chunks)
    for (int l = threadIdx.x; l < BHq * 8; l += 256) {
        int hp = l >> 3, kr = l & 7;
        if (k0 + kr < KMq)
            sbuf[kr][0][LOW + hp] = g_FB[base_i + hp * KMq + (k0 + kr)];
    }
    __syncthreads();
    const int warp = threadIdx.x >> 5, lane = threadIdx.x & 31;
    if (k0 + warp < KMq)
        fft256_warp<1>(sbuf[warp][0], sbuf[warp][1], lane);
    __syncthreads();
    // transpose-write to row-major [(bc*256+h)*103 + k]
    for (int l = threadIdx.x; l < 8 * 256; l += 256) {
        int kr = l & 7, h = l >> 3;
        int k = k0 + kr;
        if (k < KMq) {
            float2 v = sbuf[kr][0][h];
            g_FA[((size_t)bc * Hq + h) * KMq + k] = make_float2(v.x * 0.0625f, v.y * 0.0625f);
        }
    }
}

// ---------------- K5: inverse row rFFT, TWO rows per complex inverse FFT ------
// Build Z[k] = S_a[k] + i*S_b[k] (Hermitian completion; c2r drops bin-0 imag),
// one IFFT -> rows hA = re(z), hB = im(z); add residual.
__global__ __launch_bounds__(256) void k_row_inv(const float* __restrict__ x,
                                                 float* __restrict__ out) {
    __shared__ float2 sbuf[8][2][256];
    const int warp = threadIdx.x >> 5, lane = threadIdx.x & 31;
    const int bc = blockIdx.x >> 4;
    const int hA = ((blockIdx.x & 15) << 4) + 2 * warp;
    const float2* srcA = g_FA + ((size_t)bc * Hq + hA) * KMq;
    const float2* srcB = srcA + KMq;            // row hA+1
    float2* b0 = sbuf[warp][0];
#pragma unroll
    for (int j = 0; j < 8; ++j) {
        int n = lane + 32 * j;
        float2 v;
        if (n == 0) {
            v = make_float2(srcA[0].x, srcB[0].x);       // c2r: bin-0 imag dropped
        } else if (n <= 102) {
            float2 a = srcA[n], b = srcB[n];
            v = make_float2(a.x - b.y, a.y + b.x);       // S_a + i*S_b
        } else if (n >= 154) {
            float2 a = srcA[256 - n], b = srcB[256 - n];
            v = make_float2(a.x + b.y, b.x - a.y);       // conj(S_a) + i*conj(S_b)
        } else {
            v = make_float2(0.f, 0.f);                   // bins 103..153 zero
        }
        b0[n] = v;
    }
    fft256_warp<1>(b0, sbuf[warp][1], lane);
    const size_t roA = ((size_t)bc * Hq + hA) * Wq;
#pragma unroll
    for (int j = 0; j < 8; ++j) {
        int n = lane + 32 * j;
        float2 z = b0[n];
        out[roA + n]      = z.x * 0.0625f + x[roA + n];
        out[roA + Wq + n] = z.y * 0.0625f + x[roA + Wq + n];
    }
}

// ---------------- launch ----------------
extern "C" void kernel_launch(void* const* d_in, const int* in_sizes, int n_in,
                              void* d_out, int out_size) {
    const float* x  = (const float*)d_in[0];
    const float* w1 = (const float*)d_in[1];
    const float* b1 = (const float*)d_in[2];
    const float* w2 = (const float*)d_in[3];
    const float* b2 = (const float*)d_in[4];
    float* out = (float*)d_out;
    (void)in_sizes; (void)n_in; (void)out_size;

    k_prep<<<(NBq * BSq * (BSq / 2) + 255) / 256, 256>>>(w1, w2);
    k_row_fwd<<<Bq * Cq * 16, 256>>>(x);
    k_col_fwd<<<Bq * Cq * 13, 256>>>();
    k_mlp<<<Bq * NBq * NTILE, 256>>>((const float2*)b1, (const float2*)b2);
    k_col_inv<<<Bq * Cq * 13, 256>>>();
    k_row_inv<<<Bq * Cq * 16, 256>>>(x, out);
}